// round 4
// baseline (speedup 1.0000x reference)
#include <cuda_runtime.h>
#include <cstdint>

#define HIDDEN  4096
#define RANK    16
#define ROWS    4
#define THREADS 256
#define NWARP   8
#define TOTAL_ROWS 16384
#define TWO_OVER_PI 0.63661977236758134f

// Dequantized weights in device scratch (no allocations).
// g_Af[k*RANK+r] = A[k][r] * sA[r] * 2/pi ;  g_Bf[r*HIDDEN+c] = B[r][c] * sB[c]
__device__ float g_Af[HIDDEN * RANK];
__device__ float g_Bf[RANK * HIDDEN];

// --- storage-format probe (pure integer tests; FTZ/fast-math immune) ---
// mode 0 = float32 words, 1 = int32 words, 2 = packed int8 bytes
__device__ __forceinline__ int detect_mode(const void* p) {
    const unsigned* w = (const unsigned*)p;
    int vi = 0, vf = 0;
    #pragma unroll
    for (int i = 0; i < 32; i++) {
        unsigned u = w[i];
        int s = (int)u;
        if (s >= -127 && s <= 127) vi++;                    // small two's-complement int
        unsigned exp = (u >> 23) & 0xffu;
        if ((u & 0x7fffffffu) == 0u ||
            (exp >= 127u && exp <= 133u)) vf++;             // float of 1..127 magnitude (or 0)
    }
    if (vi >= 24) return 1;
    if (vf >= 24) return 0;
    return 2;
}

__device__ __forceinline__ float load_elem(const void* p, int mode, int i) {
    if (mode == 1) return (float)((const int*)p)[i];
    if (mode == 0) return ((const float*)p)[i];
    return (float)((const signed char*)p)[i];
}

__global__ void prep_kernel(const void* __restrict__ A, const void* __restrict__ B,
                            const float* __restrict__ sA, const float* __restrict__ sB)
{
    __shared__ int mA, mB;
    if (threadIdx.x == 0) { mA = detect_mode(A); mB = detect_mode(B); }
    __syncthreads();
    const int i = blockIdx.x * blockDim.x + threadIdx.x;    // exactly 65536 threads
    g_Af[i] = load_elem(A, mA, i) * sA[i & (RANK - 1)] * TWO_OVER_PI;
    g_Bf[i] = load_elem(B, mB, i) * sB[i & (HIDDEN - 1)];
}

// sin(t) via exact identity sin(t) = (-1)^q sin(t - q*pi), Cody-Waite 2-term pi,
// then degree-9 odd minimax polynomial on |r| <= pi/2 (FMA pipe only, no MUFU).
__device__ __forceinline__ float fast_sin(float t) {
    const int qi = __float2int_rn(t * 0.3183098861837907f);
    const float q = (float)qi;
    float r = fmaf(q, -3.14159274101257f, t);     // t - q*PI_HI
    r = fmaf(q, 8.742277657e-8f, r);              // + q*(PI_HI - pi)
    r = (qi & 1) ? -r : r;                        // fold sign (poly is odd)
    const float s = r * r;
    float p = 2.86567956e-6f;
    p = fmaf(p, s, -1.98559923e-4f);
    p = fmaf(p, s,  8.33338592e-3f);
    p = fmaf(p, s, -1.66666672e-1f);
    return fmaf(p, r * s, r);
}

__global__ __launch_bounds__(THREADS)
void pilora_kernel(const float* __restrict__ x, float* __restrict__ y)
{
    extern __shared__ float xs[];                 // [ROWS][HIDDEN]  64 KB
    __shared__ float red[NWARP][ROWS * RANK];
    __shared__ float hs[ROWS * RANK];

    const int tid  = threadIdx.x;
    const int lane = tid & 31;
    const int w    = tid >> 5;
    const size_t rowbase = (size_t)blockIdx.x * ROWS;

    // ---- stage x tile (coalesced float4) ----
    {
        const float4* xg4 = (const float4*)(x + rowbase * HIDDEN);
        float4* xs4 = (float4*)xs;
        #pragma unroll
        for (int i = 0; i < (ROWS * HIDDEN / 4) / THREADS; i++)
            xs4[tid + i * THREADS] = xg4[tid + i * THREADS];
    }
    __syncthreads();

    // ---- phase 1: h[row][r] = sum_k x[row][k] * Af[k][r] ----
    float acc[ROWS][RANK];
    #pragma unroll
    for (int rr = 0; rr < ROWS; rr++)
        #pragma unroll
        for (int r = 0; r < RANK; r++)
            acc[rr][r] = 0.0f;

    #pragma unroll
    for (int it = 0; it < HIDDEN / THREADS; it++) {
        const int k = it * THREADS + tid;
        const float4* arow = (const float4*)(g_Af + (size_t)k * RANK);
        const float4 a0 = arow[0], a1 = arow[1], a2 = arow[2], a3 = arow[3];
        const float av[16] = {a0.x, a0.y, a0.z, a0.w,  a1.x, a1.y, a1.z, a1.w,
                              a2.x, a2.y, a2.z, a2.w,  a3.x, a3.y, a3.z, a3.w};
        #pragma unroll
        for (int rr = 0; rr < ROWS; rr++) {
            const float xr = xs[rr * HIDDEN + k];
            #pragma unroll
            for (int r = 0; r < RANK; r++)
                acc[rr][r] = fmaf(xr, av[r], acc[rr][r]);
        }
    }

    // warp butterfly reduction; lane 0 stores per-warp partials
    #pragma unroll
    for (int rr = 0; rr < ROWS; rr++) {
        #pragma unroll
        for (int r = 0; r < RANK; r++) {
            float v = acc[rr][r];
            v += __shfl_xor_sync(0xffffffffu, v, 16);
            v += __shfl_xor_sync(0xffffffffu, v, 8);
            v += __shfl_xor_sync(0xffffffffu, v, 4);
            v += __shfl_xor_sync(0xffffffffu, v, 2);
            v += __shfl_xor_sync(0xffffffffu, v, 1);
            if (lane == 0) red[w][rr * RANK + r] = v;
        }
    }
    __syncthreads();

    if (tid < ROWS * RANK) {
        float h = 0.0f;
        #pragma unroll
        for (int ww = 0; ww < NWARP; ww++) h += red[ww][tid];
        hs[tid] = h;                       // sA and 2/pi already folded into Af
    }
    __syncthreads();

    // ---- phase 2: y = x + 2*sin( sum_r hs[row][r] * Bf[r][c] ) ----
    #pragma unroll
    for (int i = 0; i < 4; i++) {
        const int c0 = w * 512 + i * 128 + lane * 4;

        float acc2[ROWS][4];
        #pragma unroll
        for (int rr = 0; rr < ROWS; rr++)
            #pragma unroll
            for (int j = 0; j < 4; j++)
                acc2[rr][j] = 0.0f;

        #pragma unroll
        for (int r = 0; r < RANK; r++) {
            const float4 bv = *(const float4*)(g_Bf + (size_t)r * HIDDEN + c0);
            const float b[4] = {bv.x, bv.y, bv.z, bv.w};
            #pragma unroll
            for (int rr = 0; rr < ROWS; rr++) {
                const float hr = hs[rr * RANK + r];       // smem broadcast
                #pragma unroll
                for (int j = 0; j < 4; j++)
                    acc2[rr][j] = fmaf(hr, b[j], acc2[rr][j]);
            }
        }

        #pragma unroll
        for (int rr = 0; rr < ROWS; rr++) {
            const float4 xv = *(const float4*)(xs + rr * HIDDEN + c0);
            float4 ov;
            ov.x = fmaf(2.0f, fast_sin(acc2[rr][0]), xv.x);
            ov.y = fmaf(2.0f, fast_sin(acc2[rr][1]), xv.y);
            ov.z = fmaf(2.0f, fast_sin(acc2[rr][2]), xv.z);
            ov.w = fmaf(2.0f, fast_sin(acc2[rr][3]), xv.w);
            *(float4*)(y + (rowbase + rr) * HIDDEN + c0) = ov;
        }
    }
}

extern "C" void kernel_launch(void* const* d_in, const int* in_sizes, int n_in,
                              void* d_out, int out_size)
{
    // Rank-order binding by size (robust to ordering and to elements-vs-bytes):
    //   smallest -> scale_A, 2nd -> scale_B, 3rd/4th -> A,B (tie: original order), largest -> x
    int idx[16];
    const int m = (n_in < 16) ? n_in : 16;
    for (int i = 0; i < m; i++) idx[i] = i;
    for (int i = 0; i < m; i++) {
        int best = i;
        for (int j = i + 1; j < m; j++)
            if (in_sizes[idx[j]] < in_sizes[idx[best]]) best = j;
        if (best != i) {
            int t = idx[best];
            for (int j = best; j > i; j--) idx[j] = idx[j - 1];
            idx[i] = t;
        }
    }
    const float* sA = (const float*)d_in[idx[0]];
    const float* sB = (const float*)d_in[idx[1]];
    const void*  A  = d_in[idx[2]];
    const void*  B  = d_in[idx[3]];
    const float* x  = (const float*)d_in[idx[m - 1]];
    float* y = (float*)d_out;

    // 1) probe format + dequantize weights into device scratch
    prep_kernel<<<(HIDDEN * RANK) / 256, 256>>>(A, B, sA, sB);

    // 2) fused kernel
    const size_t smem = (size_t)ROWS * HIDDEN * sizeof(float);   // 64 KB
    cudaFuncSetAttribute(pilora_kernel,
                         cudaFuncAttributeMaxDynamicSharedMemorySize, (int)smem);
    pilora_kernel<<<TOTAL_ROWS / ROWS, THREADS, smem>>>(x, y);
}